// round 1
// baseline (speedup 1.0000x reference)
#include <cuda_runtime.h>
#include <math.h>

// ---------------------------------------------------------------------------
// GCGRU: graph-convolutional GRU encoder-decoder.
// Node-major layout everywhere: tensors stored (node, batch, feat).
// Per cell:
//   X = concat(x_t, h)              (N, B, din)
//   Y[k] = G[k] @ X                 (N, B, K, din)   6 big GEMMs 1024x1024xB*din
//   zr = sigmoid(Yflat @ gW + gb)   (N*B, 2H)
//   X2 = concat(x_t, r*h)
//   Y[k] = G[k] @ X2
//   h'  = z*tanh(Yflat @ uW + ub) + (1-z)*h          (fused epilogue)
// ---------------------------------------------------------------------------

#define N_    1024
#define B_    64
#define T_    12
#define HOR_  12
#define C_    2
#define H_    64
#define K_    6

#define NBH_  (N_ * B_ * H_)          // 4,194,304
#define M_    (N_ * B_)               // 65,536 rows for stage-2

#define DIN0  (C_ + H_)               // 66
#define DIN1  (2 * H_)                // 128
#define COLS0 (B_ * DIN0)             // 4224
#define COLS1 (B_ * DIN1)             // 8192
#define KD0   (K_ * DIN0)             // 396
#define KD1   (K_ * DIN1)             // 768

// ------------------------- scratch (device globals) -------------------------
__device__ float g_xT[T_ * N_ * B_ * C_];        // x transposed to (T,N,B,C)
__device__ float g_seq[T_ * N_ * B_ * H_];       // encoder layer-0 hidden seq
__device__ float g_hA[NBH_];                     // state buffer A
__device__ float g_hB[NBH_];                     // state buffer B
__device__ float g_X[N_ * B_ * DIN1];            // stage-1 GEMM input
__device__ float g_Y[N_ * B_ * K_ * DIN1];       // stage-1 GEMM output (N,B,K,din)
__device__ float g_zr[N_ * B_ * 2 * H_];         // gate activations (post-sigmoid)
__device__ float g_y[N_ * B_ * C_];              // decoder feedback (N,B,C)

// ------------------------------ kernels -------------------------------------

// x (B,T,N,C) -> g_xT (T,N,B,C)
__global__ void k_transpose_x(const float* __restrict__ x) {
    int idx = blockIdx.x * blockDim.x + threadIdx.x;
    const int total = B_ * T_ * N_ * C_;
    if (idx >= total) return;
    int c = idx % C_;
    int i = (idx / C_) % N_;
    int t = (idx / (C_ * N_)) % T_;
    int b = idx / (C_ * N_ * T_);
    g_xT[(((size_t)t * N_ + i) * B_ + b) * C_ + c] = x[idx];
}

// Build stage-1 input X (N,B,din) = concat(xin, h) or concat(xin, r*h)
__global__ void k_concat(const float* __restrict__ xin, int dinx,
                         const float* __restrict__ h,
                         const float* __restrict__ zr,   // if non-null: multiply h by r
                         int din, int total) {
    int idx = blockIdx.x * blockDim.x + threadIdx.x;
    if (idx >= total) return;
    int f = idx % din;
    int m = idx / din;
    float v;
    if (f < dinx) {
        v = xin[(size_t)m * dinx + f];
    } else {
        int j = f - dinx;
        v = h ? h[(size_t)m * H_ + j] : 0.f;
        if (zr) v *= zr[(size_t)m * (2 * H_) + H_ + j];
    }
    g_X[(size_t)m * din + f] = v;
}

// Stage-1: Y[k] = G[k] @ X.  A: (N,N) row-major; X: (N, cols) row-major.
// Output scattered into (N, B, K, din).
// Tiling: BM=BN=128, BK=8, 256 threads, 8x8 per thread.
__global__ __launch_bounds__(256)
void k_gemm1(const float* __restrict__ G, int din, int cols) {
    __shared__ float As[8][128];
    __shared__ float Bs[8][128];

    const int k  = blockIdx.z;
    const float* A = G + (size_t)k * N_ * N_;
    const int m0 = blockIdx.y * 128;
    const int n0 = blockIdx.x * 128;
    const int tid = threadIdx.x;

    const int arow = tid >> 1;           // 0..127
    const int acol = (tid & 1) << 2;     // 0 or 4
    const int brow = tid >> 5;           // 0..7
    const int bcol = (tid & 31) << 2;    // 0..124

    const int tr = (tid >> 4) << 3;      // 0..120
    const int tc = (tid & 15) << 3;      // 0..120

    float acc[8][8];
#pragma unroll
    for (int i = 0; i < 8; i++)
#pragma unroll
        for (int j = 0; j < 8; j++) acc[i][j] = 0.f;

    const float* Aptr = A + (size_t)(m0 + arow) * N_ + acol;
    const float* Bptr = g_X + (size_t)brow * cols + n0 + bcol;

    for (int kk0 = 0; kk0 < N_; kk0 += 8) {
        float4 av = *(const float4*)(Aptr + kk0);
        float4 bv = *(const float4*)(Bptr + (size_t)kk0 * cols);
        As[acol + 0][arow] = av.x;
        As[acol + 1][arow] = av.y;
        As[acol + 2][arow] = av.z;
        As[acol + 3][arow] = av.w;
        *(float4*)&Bs[brow][bcol] = bv;
        __syncthreads();

#pragma unroll
        for (int kk = 0; kk < 8; kk++) {
            float4 a0 = *(const float4*)&As[kk][tr];
            float4 a1 = *(const float4*)&As[kk][tr + 4];
            float4 b0 = *(const float4*)&Bs[kk][tc];
            float4 b1 = *(const float4*)&Bs[kk][tc + 4];
            float ar[8] = {a0.x, a0.y, a0.z, a0.w, a1.x, a1.y, a1.z, a1.w};
            float br[8] = {b0.x, b0.y, b0.z, b0.w, b1.x, b1.y, b1.z, b1.w};
#pragma unroll
            for (int i = 0; i < 8; i++)
#pragma unroll
                for (int j = 0; j < 8; j++) acc[i][j] += ar[i] * br[j];
        }
        __syncthreads();
    }

    // scatter to (N, B, K, din)
#pragma unroll
    for (int i = 0; i < 8; i++) {
        size_t mi = (size_t)(m0 + tr + i);
#pragma unroll
        for (int j = 0; j < 8; j++) {
            int n = n0 + tc + j;
            int b = n / din;
            int p = n - b * din;
            g_Y[((mi * B_ + b) * K_ + k) * din + p] = acc[i][j];
        }
    }
}

// Stage-2: out = act(Yflat @ W + bias), fused GRU math.
// Yflat: (M_, Kd) row-contiguous. W: (Kd, outd) row-major.
// mode 0: gate -> g_zr = sigmoid(.)         (outd = 128)
// mode 1: update -> hout = z*tanh(.)+(1-z)h (outd = 64)
// Tiling: BM=128, BN=64, BK=12, 256 threads, 8x4 per thread.
__global__ __launch_bounds__(256)
void k_gemm2(const float* __restrict__ W, const float* __restrict__ bias,
             int Kd, int outd, int mode,
             const float* __restrict__ hprev, float* __restrict__ hout) {
    __shared__ float As[12][128];
    __shared__ float Bs[12][64];

    const int m0 = blockIdx.y * 128;
    const int n0 = blockIdx.x * 64;
    const int tid = threadIdx.x;

    const int tr = (tid >> 4) << 3;   // 0..120
    const int tc = (tid & 15) << 2;   // 0..60

    float acc[8][4];
#pragma unroll
    for (int i = 0; i < 8; i++)
#pragma unroll
        for (int j = 0; j < 4; j++) acc[i][j] = 0.f;

    for (int kk0 = 0; kk0 < Kd; kk0 += 12) {
        // A tile: 128 rows x 12 cols = 384 float4
        for (int l = tid; l < 384; l += 256) {
            int row = l / 3;
            int c4  = (l - row * 3) << 2;
            float4 v = *(const float4*)&g_Y[(size_t)(m0 + row) * Kd + kk0 + c4];
            As[c4 + 0][row] = v.x;
            As[c4 + 1][row] = v.y;
            As[c4 + 2][row] = v.z;
            As[c4 + 3][row] = v.w;
        }
        // B tile: 12 rows x 64 cols = 192 float4
        for (int l = tid; l < 192; l += 256) {
            int row = l >> 4;
            int c4  = (l & 15) << 2;
            *(float4*)&Bs[row][c4] =
                *(const float4*)&W[(size_t)(kk0 + row) * outd + n0 + c4];
        }
        __syncthreads();

#pragma unroll
        for (int kk = 0; kk < 12; kk++) {
            float4 a0 = *(const float4*)&As[kk][tr];
            float4 a1 = *(const float4*)&As[kk][tr + 4];
            float ar[8] = {a0.x, a0.y, a0.z, a0.w, a1.x, a1.y, a1.z, a1.w};
            float4 b0 = *(const float4*)&Bs[kk][tc];
            float br[4] = {b0.x, b0.y, b0.z, b0.w};
#pragma unroll
            for (int i = 0; i < 8; i++)
#pragma unroll
                for (int j = 0; j < 4; j++) acc[i][j] += ar[i] * br[j];
        }
        __syncthreads();
    }

#pragma unroll
    for (int i = 0; i < 8; i++) {
        size_t m = (size_t)(m0 + tr + i);
#pragma unroll
        for (int j = 0; j < 4; j++) {
            int n = n0 + tc + j;
            float v = acc[i][j] + bias[n];
            if (mode == 0) {
                g_zr[m * (2 * H_) + n] = 1.f / (1.f + expf(-v));
            } else {
                float z    = g_zr[m * (2 * H_) + n];   // n < 64 here
                float hold = hprev ? hprev[m * H_ + n] : 0.f;
                hout[m * H_ + n] = z * tanhf(v) + (1.f - z) * hold;
            }
        }
    }
}

// Projection + output scatter + decoder feedback.
__global__ void k_proj(const float* __restrict__ projW,
                       const float* __restrict__ projb,
                       int t, float* __restrict__ out) {
    int m = blockIdx.x * blockDim.x + threadIdx.x;
    if (m >= M_) return;
    int i = m / B_;
    int b = m - i * B_;
    float a0 = projb[0], a1 = projb[1];
    const float* hv = &g_hB[(size_t)m * H_];
#pragma unroll
    for (int j = 0; j < H_; j++) {
        float h = hv[j];
        a0 += h * projW[j * 2 + 0];
        a1 += h * projW[j * 2 + 1];
    }
    g_y[(size_t)m * C_ + 0] = a0;
    g_y[(size_t)m * C_ + 1] = a1;
    size_t o = ((((size_t)b * HOR_ + t) * N_) + i) * C_;
    out[o + 0] = a0;
    out[o + 1] = a1;
}

// ------------------------------ host side -----------------------------------

static inline int cdiv(int a, int b) { return (a + b - 1) / b; }

struct CellW {
    const float *gW, *gb, *uW, *ub;
};

static void run_cell(const float* G,
                     const float* xin, int dinx,
                     const float* hprev, float* hout,
                     const CellW& w, int din, int cols, int Kd,
                     const float* zr_ptr) {
    int total = N_ * B_ * din;
    int cb = cdiv(total, 256);

    // gate pass
    k_concat<<<cb, 256>>>(xin, dinx, hprev, nullptr, din, total);
    dim3 g1(cols / 128, N_ / 128, K_);
    k_gemm1<<<g1, 256>>>(G, din, cols);
    dim3 g2g(2, M_ / 128);
    k_gemm2<<<g2g, 256>>>(w.gW, w.gb, Kd, 2 * H_, 0, nullptr, nullptr);

    // candidate pass
    k_concat<<<cb, 256>>>(xin, dinx, hprev, zr_ptr, din, total);
    k_gemm1<<<g1, 256>>>(G, din, cols);
    dim3 g2u(1, M_ / 128);
    k_gemm2<<<g2u, 256>>>(w.uW, w.ub, Kd, H_, 1, hprev, hout);
}

extern "C" void kernel_launch(void* const* d_in, const int* in_sizes, int n_in,
                              void* d_out, int out_size) {
    (void)in_sizes; (void)n_in; (void)out_size;

    const float* x = (const float*)d_in[0];
    const float* G = (const float*)d_in[1];
    CellW enc0 = {(const float*)d_in[2],  (const float*)d_in[3],
                  (const float*)d_in[4],  (const float*)d_in[5]};
    CellW enc1 = {(const float*)d_in[6],  (const float*)d_in[7],
                  (const float*)d_in[8],  (const float*)d_in[9]};
    CellW dec0 = {(const float*)d_in[10], (const float*)d_in[11],
                  (const float*)d_in[12], (const float*)d_in[13]};
    CellW dec1 = {(const float*)d_in[14], (const float*)d_in[15],
                  (const float*)d_in[16], (const float*)d_in[17]};
    const float* projW = (const float*)d_in[18];
    const float* projb = (const float*)d_in[19];
    float* out = (float*)d_out;

    // symbol addresses for pointer-typed kernel args
    float *p_xT, *p_seq, *p_hA, *p_hB, *p_zr, *p_y;
    cudaGetSymbolAddress((void**)&p_xT,  g_xT);
    cudaGetSymbolAddress((void**)&p_seq, g_seq);
    cudaGetSymbolAddress((void**)&p_hA,  g_hA);
    cudaGetSymbolAddress((void**)&p_hB,  g_hB);
    cudaGetSymbolAddress((void**)&p_zr,  g_zr);
    cudaGetSymbolAddress((void**)&p_y,   g_y);

    // 1) transpose input to (T,N,B,C)
    {
        int total = B_ * T_ * N_ * C_;
        k_transpose_x<<<cdiv(total, 256), 256>>>(x);
    }

    // 2) encoder layer 0: din=66, h seq kept in g_seq
    for (int t = 0; t < T_; t++) {
        const float* xin   = p_xT + (size_t)t * N_ * B_ * C_;
        const float* hprev = (t == 0) ? nullptr : p_seq + (size_t)(t - 1) * NBH_;
        float* hout        = p_seq + (size_t)t * NBH_;
        run_cell(G, xin, C_, hprev, hout, enc0, DIN0, COLS0, KD0, p_zr);
    }

    // 3) encoder layer 1: din=128, state in g_hB (in-place)
    for (int t = 0; t < T_; t++) {
        const float* xin   = p_seq + (size_t)t * NBH_;
        const float* hprev = (t == 0) ? nullptr : p_hB;
        run_cell(G, xin, H_, hprev, p_hB, enc1, DIN1, COLS1, KD1, p_zr);
    }

    // 4) decoder init: hA = enc0 last hidden; feedback y = 0
    cudaMemcpyAsync(p_hA, p_seq + (size_t)(T_ - 1) * NBH_,
                    (size_t)NBH_ * sizeof(float), cudaMemcpyDeviceToDevice);
    cudaMemsetAsync(p_y, 0, (size_t)N_ * B_ * C_ * sizeof(float));

    // 5) decoder loop
    for (int t = 0; t < HOR_; t++) {
        run_cell(G, p_y,  C_, p_hA, p_hA, dec0, DIN0, COLS0, KD0, p_zr);
        run_cell(G, p_hA, H_, p_hB, p_hB, dec1, DIN1, COLS1, KD1, p_zr);
        k_proj<<<cdiv(M_, 256), 256>>>(projW, projb, t, out);
    }
}

// round 2
// speedup vs baseline: 2.7797x; 2.7797x over previous
#include <cuda_runtime.h>
#include <math.h>
#include <stdint.h>

// ---------------------------------------------------------------------------
// GCGRU encoder-decoder, TF32 tensor-core version.
//
// Layouts:
//   g_X : (N, din, B)  feature-major stage-1 GEMM input (x-part cols [0,dinx*B),
//                      h-part cols [dinx*B, din*B) contiguous)
//   g_Y : (N*B, K, din) stage-2 GEMM input. Slots k=0,3 are identity supports,
//                      written directly by the concat kernels.
// Per cell:
//   gate:      concat_full -> gemm1(k in {1,2,4,5}, all cols) -> gemm2(sigmoid)
//   candidate: concat_h    -> gemm1(k in {1,2,4,5}, h cols)   -> gemm2(tanh+GRU)
// ---------------------------------------------------------------------------

#define N_    1024
#define B_    64
#define T_    12
#define HOR_  12
#define C_    2
#define H_    64
#define K_    6

#define NBH_  (N_ * B_ * H_)          // 4,194,304
#define M_    (N_ * B_)               // 65,536

#define DIN0  (C_ + H_)               // 66
#define DIN1  (2 * H_)                // 128
#define KD0   (K_ * DIN0)             // 396
#define KD1   (K_ * DIN1)             // 768

// ------------------------- scratch (device globals) -------------------------
__device__ float g_xT[T_ * N_ * B_ * C_];
__device__ float g_seq[T_ * N_ * B_ * H_];
__device__ float g_hA[NBH_];
__device__ float g_hB[NBH_];
__device__ float g_X[N_ * DIN1 * B_];
__device__ float g_Y[(size_t)M_ * K_ * DIN1];
__device__ float g_zr[(size_t)M_ * 2 * H_];
__device__ float g_y[M_ * C_];

// ------------------------------ helpers -------------------------------------
__device__ __forceinline__ float tf32r(float x) {
    uint32_t u;
    asm("cvt.rna.tf32.f32 %0, %1;" : "=r"(u) : "f"(x));
    return __uint_as_float(u);
}

__device__ __forceinline__ void mma_tf32(float* c, const uint32_t* a,
                                         const uint32_t* b) {
    asm volatile(
        "mma.sync.aligned.m16n8k8.row.col.f32.tf32.tf32.f32 "
        "{%0,%1,%2,%3}, {%4,%5,%6,%7}, {%8,%9}, {%0,%1,%2,%3};\n"
        : "+f"(c[0]), "+f"(c[1]), "+f"(c[2]), "+f"(c[3])
        : "r"(a[0]), "r"(a[1]), "r"(a[2]), "r"(a[3]), "r"(b[0]), "r"(b[1]));
}

// ------------------------------ kernels -------------------------------------

// x (B,T,N,C) -> g_xT (T,N,B,C)
__global__ void k_transpose_x(const float* __restrict__ x) {
    int idx = blockIdx.x * blockDim.x + threadIdx.x;
    const int total = B_ * T_ * N_ * C_;
    if (idx >= total) return;
    int c = idx % C_;
    int i = (idx / C_) % N_;
    int t = (idx / (C_ * N_)) % T_;
    int b = idx / (C_ * N_ * T_);
    g_xT[(((size_t)t * N_ + i) * B_ + b) * C_ + c] = x[idx];
}

// Gate-pass concat: build full X (N, din, B) and identity Y slots 0,3.
__global__ void k_concat_full(const float* __restrict__ xin, int dinx,
                              const float* __restrict__ h, int din) {
    int idx = blockIdx.x * blockDim.x + threadIdx.x;
    int total = N_ * din * B_;
    if (idx >= total) return;
    int b = idx % B_;
    int f = (idx / B_) % din;
    int i = idx / (B_ * din);
    int m = i * B_ + b;
    float v;
    if (f < dinx) v = xin[(size_t)m * dinx + f];
    else          v = h ? h[(size_t)m * H_ + (f - dinx)] : 0.f;
    g_X[idx] = v;
    size_t yb = (size_t)m * K_ * din;
    g_Y[yb + 0 * din + f] = v;
    g_Y[yb + 3 * din + f] = v;
}

// Candidate-pass concat: overwrite only h-part with r*h (x-part reused).
__global__ void k_concat_h(const float* __restrict__ h, int dinx, int din) {
    int idx = blockIdx.x * blockDim.x + threadIdx.x;
    int total = N_ * H_ * B_;
    if (idx >= total) return;
    int b = idx % B_;
    int j = (idx / B_) % H_;
    int i = idx / (B_ * H_);
    int m = i * B_ + b;
    int f = dinx + j;
    float v = 0.f;
    if (h) v = h[(size_t)m * H_ + j] * g_zr[(size_t)m * (2 * H_) + H_ + j];
    g_X[(size_t)i * din * B_ + (size_t)f * B_ + b] = v;
    size_t yb = (size_t)m * K_ * din;
    g_Y[yb + 0 * din + f] = v;
    g_Y[yb + 3 * din + f] = v;
}

// Stage-1: Y[k] = G[k] @ X over a column sub-range [col_off, col_off + gridX*128).
// BM=128, BN=128, BK=16, 8 warps (4x2), warp tile 32x64, tf32 mma m16n8k8.
__global__ __launch_bounds__(256)
void k_gemm1_mma(const float* __restrict__ Gfull, int col_off, int din) {
    __shared__ float As[16][132];
    __shared__ float Bs[16][132];

    const int z = blockIdx.z;
    const int kidx = (z < 2) ? z + 1 : z + 2;   // {1,2,4,5}
    const float* A = Gfull + (size_t)kidx * N_ * N_;
    const int ldx = din * B_;

    const int m0 = blockIdx.y * 128;
    const int n0 = blockIdx.x * 128;
    const int tid = threadIdx.x;
    const int lane = tid & 31;
    const int warp = tid >> 5;
    const int wm = (warp & 3) * 32;
    const int wn = (warp >> 2) * 64;
    const int gq = lane >> 2;
    const int t4 = lane & 3;

    float acc[2][8][4];
#pragma unroll
    for (int i = 0; i < 2; i++)
#pragma unroll
        for (int j = 0; j < 8; j++)
#pragma unroll
            for (int l = 0; l < 4; l++) acc[i][j][l] = 0.f;

    for (int kk0 = 0; kk0 < N_; kk0 += 16) {
        // A tile 128x16 -> As[k][m] (transposed, tf32-rounded)
#pragma unroll
        for (int i = 0; i < 2; i++) {
            int idx = tid + i * 256;          // 0..511
            int row = idx >> 2;               // 0..127
            int c4 = (idx & 3) << 2;          // 0,4,8,12
            float4 v = *(const float4*)(A + (size_t)(m0 + row) * N_ + kk0 + c4);
            As[c4 + 0][row] = tf32r(v.x);
            As[c4 + 1][row] = tf32r(v.y);
            As[c4 + 2][row] = tf32r(v.z);
            As[c4 + 3][row] = tf32r(v.w);
        }
        // B tile 16x128 -> Bs[k][n]
#pragma unroll
        for (int i = 0; i < 2; i++) {
            int idx = tid + i * 256;
            int r = idx >> 5;                 // 0..15
            int c4 = (idx & 31) << 2;         // 0..124
            float4 v = *(const float4*)(g_X + (size_t)(kk0 + r) * ldx +
                                        col_off + n0 + c4);
            Bs[r][c4 + 0] = tf32r(v.x);
            Bs[r][c4 + 1] = tf32r(v.y);
            Bs[r][c4 + 2] = tf32r(v.z);
            Bs[r][c4 + 3] = tf32r(v.w);
        }
        __syncthreads();

#pragma unroll
        for (int ks = 0; ks < 2; ks++) {
            const int kb = ks * 8;
            uint32_t a[2][4], b[8][2];
#pragma unroll
            for (int mt = 0; mt < 2; mt++) {
                int r = wm + mt * 16 + gq;
                a[mt][0] = __float_as_uint(As[kb + t4][r]);
                a[mt][1] = __float_as_uint(As[kb + t4][r + 8]);
                a[mt][2] = __float_as_uint(As[kb + t4 + 4][r]);
                a[mt][3] = __float_as_uint(As[kb + t4 + 4][r + 8]);
            }
#pragma unroll
            for (int nt = 0; nt < 8; nt++) {
                int c = wn + nt * 8 + gq;
                b[nt][0] = __float_as_uint(Bs[kb + t4][c]);
                b[nt][1] = __float_as_uint(Bs[kb + t4 + 4][c]);
            }
#pragma unroll
            for (int mt = 0; mt < 2; mt++)
#pragma unroll
                for (int nt = 0; nt < 8; nt++)
                    mma_tf32(acc[mt][nt], a[mt], b[nt]);
        }
        __syncthreads();
    }

    // scatter: xcol -> (f = xcol/64, b = xcol%64); Y[(m*B+b)*K + kidx][f]
#pragma unroll
    for (int mt = 0; mt < 2; mt++) {
        int row = m0 + wm + mt * 16 + gq;
#pragma unroll
        for (int nt = 0; nt < 8; nt++) {
            int xcol = col_off + n0 + wn + nt * 8 + t4 * 2;
#pragma unroll
            for (int hh = 0; hh < 2; hh++) {     // row, row+8
                int rr = row + hh * 8;
#pragma unroll
                for (int cc = 0; cc < 2; cc++) { // xcol, xcol+1
                    int xc = xcol + cc;
                    int f = xc >> 6;
                    int bb = xc & 63;
                    g_Y[(((size_t)rr * B_ + bb) * K_ + kidx) * din + f] =
                        acc[mt][nt][hh * 2 + cc];
                }
            }
        }
    }
}

// Stage-2: act(Yflat @ W + bias) with fused GRU epilogue. tf32 mma.
// BM=128, BN=64, BK=16, 8 warps (4x2), warp tile 32x32.
// mode 0: g_zr = sigmoid(.) (outd=128); mode 1: hout = z*tanh(.)+(1-z)h (outd=64)
__global__ __launch_bounds__(256)
void k_gemm2_mma(const float* __restrict__ W, const float* __restrict__ bias,
                 int Kd, int outd, int mode,
                 const float* __restrict__ hprev, float* __restrict__ hout) {
    __shared__ float As[16][132];
    __shared__ float Bs[16][68];

    const int m0 = blockIdx.y * 128;
    const int n0 = blockIdx.x * 64;
    const int tid = threadIdx.x;
    const int lane = tid & 31;
    const int warp = tid >> 5;
    const int wm = (warp & 3) * 32;
    const int wn = (warp >> 2) * 32;
    const int gq = lane >> 2;
    const int t4 = lane & 3;

    float acc[2][4][4];
#pragma unroll
    for (int i = 0; i < 2; i++)
#pragma unroll
        for (int j = 0; j < 4; j++)
#pragma unroll
            for (int l = 0; l < 4; l++) acc[i][j][l] = 0.f;

    const int ksteps = (Kd + 15) / 16;
    for (int kt = 0; kt < ksteps; kt++) {
        const int kk0 = kt * 16;
        // A tile 128x16 from g_Y (row stride Kd), guarded, tf32-rounded
#pragma unroll
        for (int i = 0; i < 2; i++) {
            int idx = tid + i * 256;
            int row = idx >> 2;
            int c4 = (idx & 3) << 2;
            float4 v = make_float4(0.f, 0.f, 0.f, 0.f);
            if (kk0 + c4 < Kd)   // Kd % 4 == 0 so float4 fully in/out
                v = *(const float4*)(g_Y + (size_t)(m0 + row) * Kd + kk0 + c4);
            As[c4 + 0][row] = tf32r(v.x);
            As[c4 + 1][row] = tf32r(v.y);
            As[c4 + 2][row] = tf32r(v.z);
            As[c4 + 3][row] = tf32r(v.w);
        }
        // B tile 16x64 from W (row stride outd), guarded
        {
            int r = tid >> 4;                 // 0..15
            int c4 = (tid & 15) << 2;         // 0..60
            float4 v = make_float4(0.f, 0.f, 0.f, 0.f);
            if (kk0 + r < Kd)
                v = *(const float4*)(W + (size_t)(kk0 + r) * outd + n0 + c4);
            Bs[r][c4 + 0] = tf32r(v.x);
            Bs[r][c4 + 1] = tf32r(v.y);
            Bs[r][c4 + 2] = tf32r(v.z);
            Bs[r][c4 + 3] = tf32r(v.w);
        }
        __syncthreads();

#pragma unroll
        for (int ks = 0; ks < 2; ks++) {
            const int kb = ks * 8;
            uint32_t a[2][4], b[4][2];
#pragma unroll
            for (int mt = 0; mt < 2; mt++) {
                int r = wm + mt * 16 + gq;
                a[mt][0] = __float_as_uint(As[kb + t4][r]);
                a[mt][1] = __float_as_uint(As[kb + t4][r + 8]);
                a[mt][2] = __float_as_uint(As[kb + t4 + 4][r]);
                a[mt][3] = __float_as_uint(As[kb + t4 + 4][r + 8]);
            }
#pragma unroll
            for (int nt = 0; nt < 4; nt++) {
                int c = wn + nt * 8 + gq;
                b[nt][0] = __float_as_uint(Bs[kb + t4][c]);
                b[nt][1] = __float_as_uint(Bs[kb + t4 + 4][c]);
            }
#pragma unroll
            for (int mt = 0; mt < 2; mt++)
#pragma unroll
                for (int nt = 0; nt < 4; nt++)
                    mma_tf32(acc[mt][nt], a[mt], b[nt]);
        }
        __syncthreads();
    }

#pragma unroll
    for (int mt = 0; mt < 2; mt++) {
        int row = m0 + wm + mt * 16 + gq;
#pragma unroll
        for (int nt = 0; nt < 4; nt++) {
            int nb = n0 + wn + nt * 8 + t4 * 2;
#pragma unroll
            for (int hh = 0; hh < 2; hh++) {
                size_t m = (size_t)(row + hh * 8);
#pragma unroll
                for (int cc = 0; cc < 2; cc++) {
                    int n = nb + cc;
                    float v = acc[mt][nt][hh * 2 + cc] + bias[n];
                    if (mode == 0) {
                        g_zr[m * (2 * H_) + n] = 1.f / (1.f + expf(-v));
                    } else {
                        float z = g_zr[m * (2 * H_) + n];
                        float hold = hprev ? hprev[m * H_ + n] : 0.f;
                        hout[m * H_ + n] = z * tanhf(v) + (1.f - z) * hold;
                    }
                }
            }
        }
    }
}

// Projection + output scatter + decoder feedback.
__global__ void k_proj(const float* __restrict__ projW,
                       const float* __restrict__ projb,
                       int t, float* __restrict__ out) {
    int m = blockIdx.x * blockDim.x + threadIdx.x;
    if (m >= M_) return;
    int i = m / B_;
    int b = m - i * B_;
    float a0 = projb[0], a1 = projb[1];
    const float* hv = &g_hB[(size_t)m * H_];
#pragma unroll
    for (int j = 0; j < H_; j++) {
        float h = hv[j];
        a0 += h * projW[j * 2 + 0];
        a1 += h * projW[j * 2 + 1];
    }
    g_y[(size_t)m * C_ + 0] = a0;
    g_y[(size_t)m * C_ + 1] = a1;
    size_t o = ((((size_t)b * HOR_ + t) * N_) + i) * C_;
    out[o + 0] = a0;
    out[o + 1] = a1;
}

// ------------------------------ host side -----------------------------------

static inline int cdiv(int a, int b) { return (a + b - 1) / b; }

struct CellW {
    const float *gW, *gb, *uW, *ub;
};

static void run_cell(const float* G,
                     const float* xin, int dinx,
                     const float* hprev, float* hout,
                     const CellW& w, int din, int Kd) {
    const int cols = din * B_;

    // gate pass
    k_concat_full<<<cdiv(N_ * din * B_, 256), 256>>>(xin, dinx, hprev, din);
    dim3 g1(cols / 128, N_ / 128, 4);
    k_gemm1_mma<<<g1, 256>>>(G, 0, din);
    k_gemm2_mma<<<dim3(2, M_ / 128), 256>>>(w.gW, w.gb, Kd, 2 * H_, 0,
                                            nullptr, nullptr);

    // candidate pass: only h columns recomputed
    k_concat_h<<<cdiv(N_ * H_ * B_, 256), 256>>>(hprev, dinx, din);
    dim3 g1h((H_ * B_) / 128, N_ / 128, 4);
    k_gemm1_mma<<<g1h, 256>>>(G, dinx * B_, din);
    k_gemm2_mma<<<dim3(1, M_ / 128), 256>>>(w.uW, w.ub, Kd, H_, 1,
                                            hprev, hout);
}

extern "C" void kernel_launch(void* const* d_in, const int* in_sizes, int n_in,
                              void* d_out, int out_size) {
    (void)in_sizes; (void)n_in; (void)out_size;

    const float* x = (const float*)d_in[0];
    const float* G = (const float*)d_in[1];
    CellW enc0 = {(const float*)d_in[2],  (const float*)d_in[3],
                  (const float*)d_in[4],  (const float*)d_in[5]};
    CellW enc1 = {(const float*)d_in[6],  (const float*)d_in[7],
                  (const float*)d_in[8],  (const float*)d_in[9]};
    CellW dec0 = {(const float*)d_in[10], (const float*)d_in[11],
                  (const float*)d_in[12], (const float*)d_in[13]};
    CellW dec1 = {(const float*)d_in[14], (const float*)d_in[15],
                  (const float*)d_in[16], (const float*)d_in[17]};
    const float* projW = (const float*)d_in[18];
    const float* projb = (const float*)d_in[19];
    float* out = (float*)d_out;

    float *p_xT, *p_seq, *p_hA, *p_hB, *p_y;
    cudaGetSymbolAddress((void**)&p_xT,  g_xT);
    cudaGetSymbolAddress((void**)&p_seq, g_seq);
    cudaGetSymbolAddress((void**)&p_hA,  g_hA);
    cudaGetSymbolAddress((void**)&p_hB,  g_hB);
    cudaGetSymbolAddress((void**)&p_y,   g_y);

    {
        int total = B_ * T_ * N_ * C_;
        k_transpose_x<<<cdiv(total, 256), 256>>>(x);
    }

    // encoder layer 0 (din=66)
    for (int t = 0; t < T_; t++) {
        const float* xin   = p_xT + (size_t)t * N_ * B_ * C_;
        const float* hprev = (t == 0) ? nullptr : p_seq + (size_t)(t - 1) * NBH_;
        float* hout        = p_seq + (size_t)t * NBH_;
        run_cell(G, xin, C_, hprev, hout, enc0, DIN0, KD0);
    }

    // encoder layer 1 (din=128)
    for (int t = 0; t < T_; t++) {
        const float* xin   = p_seq + (size_t)t * NBH_;
        const float* hprev = (t == 0) ? nullptr : p_hB;
        run_cell(G, xin, H_, hprev, p_hB, enc1, DIN1, KD1);
    }

    // decoder init
    cudaMemcpyAsync(p_hA, p_seq + (size_t)(T_ - 1) * NBH_,
                    (size_t)NBH_ * sizeof(float), cudaMemcpyDeviceToDevice);
    cudaMemsetAsync(p_y, 0, (size_t)M_ * C_ * sizeof(float));

    // decoder loop
    for (int t = 0; t < HOR_; t++) {
        run_cell(G, p_y,  C_, p_hA, p_hA, dec0, DIN0, KD0);
        run_cell(G, p_hA, H_, p_hB, p_hB, dec1, DIN1, KD1);
        k_proj<<<cdiv(M_, 256), 256>>>(projW, projb, t, out);
    }
}

// round 4
// speedup vs baseline: 4.3638x; 1.5699x over previous
#include <cuda_runtime.h>
#include <math.h>
#include <stdint.h>

// ---------------------------------------------------------------------------
// GCGRU encoder-decoder, TF32 tensor cores, cp.async double-buffered GEMMs.
//
// Layouts:
//   g_X*  : (N, din_p, B)   stage-1 input, TF32-rounded, pad cols zero
//   g_Y*  : (slot, N, din_p, B) stage-1 output for supports {1,2,4,5},
//           TF32-rounded; identity supports (0,3) read from g_X directly.
//   g_Gt  : 4 supports, TF32-rounded, (slot, N, N)
//   g_Wp  : padded (K*din_p, outd) TF32-rounded weights
// ---------------------------------------------------------------------------

#define N_    1024
#define B_    64
#define T_    12
#define HOR_  12
#define C_    2
#define H_    64
#define K_    6

#define NBH_  (N_ * B_ * H_)
#define M_    (N_ * B_)

#define DINR0 66
#define DINP0 80
#define DINR1 128
#define DINP1 128

// ------------------------- scratch (device globals) -------------------------
__device__ float g_xT[T_ * N_ * B_ * C_];
__device__ float g_seq[T_ * N_ * B_ * H_];
__device__ float g_hA[NBH_];
__device__ float g_hB[NBH_];
__device__ float g_X0[N_ * DINP0 * B_];
__device__ float g_X1[N_ * DINP1 * B_];
__device__ float g_Y0[4ll * N_ * DINP0 * B_];
__device__ float g_Y1[4ll * N_ * DINP1 * B_];
__device__ float g_zr[(size_t)M_ * 2 * H_];
__device__ float g_y[M_ * C_];
__device__ float g_Gt[4 * N_ * N_];
__device__ float g_Wp[479232];

// ------------------------------ helpers -------------------------------------
__device__ __forceinline__ float tf32r(float x) {
    uint32_t u;
    asm("cvt.rna.tf32.f32 %0, %1;" : "=r"(u) : "f"(x));
    return __uint_as_float(u);
}

__device__ __forceinline__ void mma_tf32(float* c, const uint32_t* a,
                                         const uint32_t* b) {
    asm volatile(
        "mma.sync.aligned.m16n8k8.row.col.f32.tf32.tf32.f32 "
        "{%0,%1,%2,%3}, {%4,%5,%6,%7}, {%8,%9}, {%0,%1,%2,%3};\n"
        : "+f"(c[0]), "+f"(c[1]), "+f"(c[2]), "+f"(c[3])
        : "r"(a[0]), "r"(a[1]), "r"(a[2]), "r"(a[3]), "r"(b[0]), "r"(b[1]));
}

__device__ __forceinline__ void cp16(void* dst, const void* src) {
    uint32_t d = (uint32_t)__cvta_generic_to_shared(dst);
    asm volatile("cp.async.ca.shared.global [%0], [%1], 16;\n"
                 :: "r"(d), "l"(src));
}
__device__ __forceinline__ void cp_commit() {
    asm volatile("cp.async.commit_group;\n");
}
template <int n>
__device__ __forceinline__ void cp_wait() {
    asm volatile("cp.async.wait_group %0;\n" :: "n"(n));
}

// ------------------------------ prep kernels --------------------------------

__global__ void k_prep_G(const float* __restrict__ G) {
    int idx = blockIdx.x * blockDim.x + threadIdx.x;
    if (idx >= 4 * N_ * N_) return;
    int s = idx / (N_ * N_);
    int r = idx - s * (N_ * N_);
    int kidx = s + 1 + (s >> 1);   // {1,2,4,5}
    g_Gt[idx] = tf32r(G[(size_t)kidx * N_ * N_ + r]);
}

__global__ void k_prep_W(const float* __restrict__ src, float* __restrict__ dst,
                         int din_r, int din_p, int outd) {
    int idx = blockIdx.x * blockDim.x + threadIdx.x;
    int total = K_ * din_p * outd;
    if (idx >= total) return;
    int o = idx % outd;
    int row = idx / outd;
    int k = row / din_p;
    int f = row - k * din_p;
    dst[idx] = (f < din_r) ? tf32r(src[(size_t)(k * din_r + f) * outd + o]) : 0.f;
}

// ------------------------------ data movement -------------------------------

// x (B,T,N,C) -> g_xT (T,N,B,C)
__global__ void k_transpose_x(const float* __restrict__ x) {
    int idx = blockIdx.x * blockDim.x + threadIdx.x;
    const int total = B_ * T_ * N_ * C_;
    if (idx >= total) return;
    int c = idx % C_;
    int i = (idx / C_) % N_;
    int t = (idx / (C_ * N_)) % T_;
    int b = idx / (C_ * N_ * T_);
    g_xT[(((size_t)t * N_ + i) * B_ + b) * C_ + c] = x[idx];
}

// Gate-pass concat: X[i][f][b], f < din_r, TF32-rounded.
__global__ void k_concat_full(const float* __restrict__ xin, int dinx,
                              const float* __restrict__ h,
                              float* __restrict__ X, int din_r, int din_p) {
    int idx = blockIdx.x * blockDim.x + threadIdx.x;
    int total = N_ * din_r * B_;
    if (idx >= total) return;
    int b = idx & 63;
    int f = (idx >> 6) % din_r;
    int i = idx / (64 * din_r);
    int m = i * B_ + b;
    float v;
    if (f < dinx) v = xin[(size_t)m * dinx + f];
    else          v = h ? h[(size_t)m * H_ + (f - dinx)] : 0.f;
    X[((size_t)i * din_p + f) * B_ + b] = tf32r(v);
}

// Candidate-pass concat: overwrite h-part with r*h.
__global__ void k_concat_h(const float* __restrict__ h, int dinx,
                           float* __restrict__ X, int din_p) {
    int idx = blockIdx.x * blockDim.x + threadIdx.x;
    int total = N_ * H_ * B_;
    if (idx >= total) return;
    int b = idx & 63;
    int j = (idx >> 6) & 63;
    int i = idx >> 12;
    int m = i * B_ + b;
    float v = 0.f;
    if (h) v = h[(size_t)m * H_ + j] * g_zr[(size_t)m * (2 * H_) + H_ + j];
    X[((size_t)i * din_p + (dinx + j)) * B_ + b] = tf32r(v);
}

// ------------------------------ stage-1 GEMM --------------------------------
// Y[s] = G[s] @ X over columns [col_off, col_off + gridX*128).
// BM=128, BN=128, BK=16, 8 warps (4x2), warp tile 32x64. cp.async 2-stage.
__global__ __launch_bounds__(256)
void k_gemm1(const float* __restrict__ Gt, const float* __restrict__ X,
             float* __restrict__ Y, int col_off, int ldp) {
    __shared__ __align__(16) float As[2][128][20];
    __shared__ __align__(16) float Bs[2][16][132];

    const int s = blockIdx.z;
    const float* A = Gt + (size_t)s * N_ * N_;
    const int m0 = blockIdx.y * 128;
    const int n0 = col_off + blockIdx.x * 128;
    const int tid = threadIdx.x;
    const int lane = tid & 31;
    const int warp = tid >> 5;
    const int wm = (warp & 3) * 32;
    const int wn = (warp >> 2) * 64;
    const int gq = lane >> 2;
    const int t4 = lane & 3;

    float acc[2][8][4];
#pragma unroll
    for (int i = 0; i < 2; i++)
#pragma unroll
        for (int j = 0; j < 8; j++)
#pragma unroll
            for (int l = 0; l < 4; l++) acc[i][j][l] = 0.f;

    auto load_stage = [&](int buf, int kk0) {
#pragma unroll
        for (int i = 0; i < 2; i++) {
            int idx = tid + i * 256;          // 0..511
            int row = idx >> 2;
            int j = (idx & 3) << 2;
            cp16(&As[buf][row][j], A + (size_t)(m0 + row) * N_ + kk0 + j);
        }
#pragma unroll
        for (int i = 0; i < 2; i++) {
            int idx = tid + i * 256;
            int r = idx >> 5;
            int j = (idx & 31) << 2;
            cp16(&Bs[buf][r][j], X + (size_t)(kk0 + r) * ldp + n0 + j);
        }
    };

    load_stage(0, 0);
    cp_commit();

    const int KSTEPS = N_ / 16;
    for (int kt = 0; kt < KSTEPS; kt++) {
        int buf = kt & 1;
        if (kt + 1 < KSTEPS) {
            load_stage(buf ^ 1, (kt + 1) * 16);
            cp_commit();
            cp_wait<1>();
        } else {
            cp_wait<0>();
        }
        __syncthreads();

#pragma unroll
        for (int ks = 0; ks < 2; ks++) {
            const int kb = ks * 8;
            uint32_t a[2][4], b[8][2];
#pragma unroll
            for (int mt = 0; mt < 2; mt++) {
                int r = wm + mt * 16 + gq;
                a[mt][0] = __float_as_uint(As[buf][r][kb + t4]);
                a[mt][1] = __float_as_uint(As[buf][r + 8][kb + t4]);
                a[mt][2] = __float_as_uint(As[buf][r][kb + t4 + 4]);
                a[mt][3] = __float_as_uint(As[buf][r + 8][kb + t4 + 4]);
            }
#pragma unroll
            for (int nt = 0; nt < 8; nt++) {
                int c = wn + nt * 8 + gq;
                b[nt][0] = __float_as_uint(Bs[buf][kb + t4][c]);
                b[nt][1] = __float_as_uint(Bs[buf][kb + t4 + 4][c]);
            }
#pragma unroll
            for (int mt = 0; mt < 2; mt++)
#pragma unroll
                for (int nt = 0; nt < 8; nt++)
                    mma_tf32(acc[mt][nt], a[mt], b[nt]);
        }
        __syncthreads();
    }

    // coalesced float2 stores, TF32-rounded (Y feeds stage-2 A via cp.async)
#pragma unroll
    for (int mt = 0; mt < 2; mt++) {
        int row = m0 + wm + mt * 16 + gq;
#pragma unroll
        for (int nt = 0; nt < 8; nt++) {
            int xcol = n0 + wn + nt * 8 + t4 * 2;
#pragma unroll
            for (int hh = 0; hh < 2; hh++) {
                int rr = row + hh * 8;
                float2 v;
                v.x = tf32r(acc[mt][nt][hh * 2 + 0]);
                v.y = tf32r(acc[mt][nt][hh * 2 + 1]);
                *(float2*)&Y[((size_t)s * N_ + rr) * ldp + xcol] = v;
            }
        }
    }
}

// ------------------------------ stage-2 GEMM --------------------------------
// out = act(A @ W + bias); A rows m=(i,b), cols (k,f) padded.
// A chunks come from g_X (k=0,3) or g_Y slot (k=1,2,4,5).
// BM=128 (2 nodes), BN=64, BK=16, 8 warps (4x2), warp tile 32x32. cp.async.
// mode 0: g_zr = sigmoid(.); mode 1: hout = z*tanh(.)+(1-z)*h.
__global__ __launch_bounds__(256)
void k_gemm2(const float* __restrict__ Xp, const float* __restrict__ Yp,
             const float* __restrict__ W, const float* __restrict__ bias,
             int din_p, int outd, int mode,
             const float* __restrict__ hprev, float* __restrict__ hout) {
    __shared__ __align__(16) float As[2][16][132];
    __shared__ __align__(16) float Bs[2][16][68];

    const int m0 = blockIdx.y * 128;
    const int i0 = m0 >> 6;            // base node (2 nodes per block)
    const int n0 = blockIdx.x * 64;
    const int tid = threadIdx.x;
    const int lane = tid & 31;
    const int warp = tid >> 5;
    const int wm = (warp & 3) * 32;
    const int wn = (warp >> 2) * 32;
    const int gq = lane >> 2;
    const int t4 = lane & 3;
    const int ldp = din_p * B_;

    float acc[2][4][4];
#pragma unroll
    for (int i = 0; i < 2; i++)
#pragma unroll
        for (int j = 0; j < 4; j++)
#pragma unroll
            for (int l = 0; l < 4; l++) acc[i][j][l] = 0.f;

    auto load_stage = [&](int buf, int kt) {
        int kk0 = kt * 16;
        int k = kk0 / din_p;
        int f0 = kk0 - k * din_p;
        const float* basep;
        if (k == 0 || k == 3) basep = Xp;
        else basep = Yp + (size_t)((k < 3) ? k - 1 : k - 2) * N_ * ldp;
#pragma unroll
        for (int i = 0; i < 2; i++) {
            int idx = tid + i * 256;          // 0..511
            int j = idx >> 5;                 // f row 0..15
            int q = idx & 31;                 // chunk
            int node = q >> 4;
            int ch = (q & 15) << 2;
            cp16(&As[buf][j][node * 64 + ch],
                 basep + ((size_t)(i0 + node) * din_p + f0 + j) * B_ + ch);
        }
        // W tile 16x64: all 256 threads, 4 floats each
        {
            int r = tid >> 4;                 // 0..15
            int ch = (tid & 15) << 2;         // 0..60
            cp16(&Bs[buf][r][ch], W + (size_t)(kk0 + r) * outd + n0 + ch);
        }
    };

    load_stage(0, 0);
    cp_commit();

    const int KSTEPS = (K_ * din_p) >> 4;
    for (int kt = 0; kt < KSTEPS; kt++) {
        int buf = kt & 1;
        if (kt + 1 < KSTEPS) {
            load_stage(buf ^ 1, kt + 1);
            cp_commit();
            cp_wait<1>();
        } else {
            cp_wait<0>();
        }
        __syncthreads();

#pragma unroll
        for (int ks = 0; ks < 2; ks++) {
            const int kb = ks * 8;
            uint32_t a[2][4], b[4][2];
#pragma unroll
            for (int mt = 0; mt < 2; mt++) {
                int r = wm + mt * 16 + gq;
                a[mt][0] = __float_as_uint(As[buf][kb + t4][r]);
                a[mt][1] = __float_as_uint(As[buf][kb + t4][r + 8]);
                a[mt][2] = __float_as_uint(As[buf][kb + t4 + 4][r]);
                a[mt][3] = __float_as_uint(As[buf][kb + t4 + 4][r + 8]);
            }
#pragma unroll
            for (int nt = 0; nt < 4; nt++) {
                int c = wn + nt * 8 + gq;
                b[nt][0] = __float_as_uint(Bs[buf][kb + t4][c]);
                b[nt][1] = __float_as_uint(Bs[buf][kb + t4 + 4][c]);
            }
#pragma unroll
            for (int mt = 0; mt < 2; mt++)
#pragma unroll
                for (int nt = 0; nt < 4; nt++)
                    mma_tf32(acc[mt][nt], a[mt], b[nt]);
        }
        __syncthreads();
    }

#pragma unroll
    for (int mt = 0; mt < 2; mt++) {
        int row = m0 + wm + mt * 16 + gq;
#pragma unroll
        for (int nt = 0; nt < 4; nt++) {
            int nb = n0 + wn + nt * 8 + t4 * 2;
#pragma unroll
            for (int hh = 0; hh < 2; hh++) {
                size_t m = (size_t)(row + hh * 8);
#pragma unroll
                for (int cc = 0; cc < 2; cc++) {
                    int n = nb + cc;
                    float v = acc[mt][nt][hh * 2 + cc] + bias[n];
                    if (mode == 0) {
                        g_zr[m * (2 * H_) + n] = 1.f / (1.f + expf(-v));
                    } else {
                        float z = g_zr[m * (2 * H_) + n];
                        float hold = hprev ? hprev[m * H_ + n] : 0.f;
                        hout[m * H_ + n] = z * tanhf(v) + (1.f - z) * hold;
                    }
                }
            }
        }
    }
}

// Projection + output scatter + decoder feedback.
__global__ void k_proj(const float* __restrict__ projW,
                       const float* __restrict__ projb,
                       int t, float* __restrict__ out) {
    int m = blockIdx.x * blockDim.x + threadIdx.x;
    if (m >= M_) return;
    int i = m / B_;
    int b = m - i * B_;
    float a0 = projb[0], a1 = projb[1];
    const float* hv = &g_hB[(size_t)m * H_];
#pragma unroll
    for (int j = 0; j < H_; j++) {
        float h = hv[j];
        a0 += h * projW[j * 2 + 0];
        a1 += h * projW[j * 2 + 1];
    }
    g_y[(size_t)m * C_ + 0] = a0;
    g_y[(size_t)m * C_ + 1] = a1;
    size_t o = ((((size_t)b * HOR_ + t) * N_) + i) * C_;
    out[o + 0] = a0;
    out[o + 1] = a1;
}

// ------------------------------ host side -----------------------------------

static inline int cdiv(int a, int b) { return (a + b - 1) / b; }

// padded weight offsets inside g_Wp
#define OFF_E0G 0
#define OFF_E0U 61440
#define OFF_D0G 92160
#define OFF_D0U 153600
#define OFF_E1G 184320
#define OFF_E1U 282624
#define OFF_D1G 331776
#define OFF_D1U 430080

static void run_cell(const float* Gt,
                     const float* xin, int dinx,
                     const float* hprev, float* hout,
                     const float* Wg, const float* bg,
                     const float* Wu, const float* bu,
                     float* Xp, float* Yp, int din_r, int din_p) {
    const int ldp = din_p * B_;

    // gate pass
    k_concat_full<<<cdiv(N_ * din_r * B_, 256), 256>>>(xin, dinx, hprev,
                                                       Xp, din_r, din_p);
    dim3 g1((din_r * B_) / 128, N_ / 128, 4);
    k_gemm1<<<g1, 256>>>(Gt, Xp, Yp, 0, ldp);
    k_gemm2<<<dim3(2, M_ / 128), 256>>>(Xp, Yp, Wg, bg, din_p, 2 * H_, 0,
                                        nullptr, nullptr);

    // candidate pass: only h columns recomputed
    k_concat_h<<<cdiv(N_ * H_ * B_, 256), 256>>>(hprev, dinx, Xp, din_p);
    dim3 g1h((H_ * B_) / 128, N_ / 128, 4);
    k_gemm1<<<g1h, 256>>>(Gt, Xp, Yp, dinx * B_, ldp);
    k_gemm2<<<dim3(1, M_ / 128), 256>>>(Xp, Yp, Wu, bu, din_p, H_, 1,
                                        hprev, hout);
}

extern "C" void kernel_launch(void* const* d_in, const int* in_sizes, int n_in,
                              void* d_out, int out_size) {
    (void)in_sizes; (void)n_in; (void)out_size;

    const float* x = (const float*)d_in[0];
    const float* G = (const float*)d_in[1];
    const float* w[16];
    for (int i = 0; i < 16; i++) w[i] = (const float*)d_in[2 + i];
    const float* projW = (const float*)d_in[18];
    const float* projb = (const float*)d_in[19];
    float* out = (float*)d_out;

    float *p_xT, *p_seq, *p_hA, *p_hB, *p_y, *p_X0, *p_X1, *p_Y0, *p_Y1,
          *p_Gt, *p_Wp;
    cudaGetSymbolAddress((void**)&p_xT,  g_xT);
    cudaGetSymbolAddress((void**)&p_seq, g_seq);
    cudaGetSymbolAddress((void**)&p_hA,  g_hA);
    cudaGetSymbolAddress((void**)&p_hB,  g_hB);
    cudaGetSymbolAddress((void**)&p_y,   g_y);
    cudaGetSymbolAddress((void**)&p_X0,  g_X0);
    cudaGetSymbolAddress((void**)&p_X1,  g_X1);
    cudaGetSymbolAddress((void**)&p_Y0,  g_Y0);
    cudaGetSymbolAddress((void**)&p_Y1,  g_Y1);
    cudaGetSymbolAddress((void**)&p_Gt,  g_Gt);
    cudaGetSymbolAddress((void**)&p_Wp,  g_Wp);

    // prep: round G, pad+round weights
    k_prep_G<<<cdiv(4 * N_ * N_, 256), 256>>>(G);
    k_prep_W<<<cdiv(K_ * DINP0 * 128, 256), 256>>>(w[0],  p_Wp + OFF_E0G, DINR0, DINP0, 128);
    k_prep_W<<<cdiv(K_ * DINP0 *  64, 256), 256>>>(w[2],  p_Wp + OFF_E0U, DINR0, DINP0,  64);
    k_prep_W<<<cdiv(K_ * DINP1 * 128, 256), 256>>>(w[4],  p_Wp + OFF_E1G, DINR1, DINP1, 128);
    k_prep_W<<<cdiv(K_ * DINP1 *  64, 256), 256>>>(w[6],  p_Wp + OFF_E1U, DINR1, DINP1,  64);
    k_prep_W<<<cdiv(K_ * DINP0 * 128, 256), 256>>>(w[8],  p_Wp + OFF_D0G, DINR0, DINP0, 128);
    k_prep_W<<<cdiv(K_ * DINP0 *  64, 256), 256>>>(w[10], p_Wp + OFF_D0U, DINR0, DINP0,  64);
    k_prep_W<<<cdiv(K_ * DINP1 * 128, 256), 256>>>(w[12], p_Wp + OFF_D1G, DINR1, DINP1, 128);
    k_prep_W<<<cdiv(K_ * DINP1 *  64, 256), 256>>>(w[14], p_Wp + OFF_D1U, DINR1, DINP1,  64);

    {
        int total = B_ * T_ * N_ * C_;
        k_transpose_x<<<cdiv(total, 256), 256>>>(x);
    }

    // encoder layer 0 (din 66 -> padded 80)
    for (int t = 0; t < T_; t++) {
        const float* xin   = p_xT + (size_t)t * N_ * B_ * C_;
        const float* hprev = (t == 0) ? nullptr : p_seq + (size_t)(t - 1) * NBH_;
        float* hout        = p_seq + (size_t)t * NBH_;
        run_cell(p_Gt, xin, C_, hprev, hout,
                 p_Wp + OFF_E0G, w[1], p_Wp + OFF_E0U, w[3],
                 p_X0, p_Y0, DINR0, DINP0);
    }

    // encoder layer 1 (din 128)
    for (int t = 0; t < T_; t++) {
        const float* xin   = p_seq + (size_t)t * NBH_;
        const float* hprev = (t == 0) ? nullptr : p_hB;
        run_cell(p_Gt, xin, H_, hprev, p_hB,
                 p_Wp + OFF_E1G, w[5], p_Wp + OFF_E1U, w[7],
                 p_X1, p_Y1, DINR1, DINP1);
    }

    // decoder init
    cudaMemcpyAsync(p_hA, p_seq + (size_t)(T_ - 1) * NBH_,
                    (size_t)NBH_ * sizeof(float), cudaMemcpyDeviceToDevice);
    cudaMemsetAsync(p_y, 0, (size_t)M_ * C_ * sizeof(float));

    // decoder loop
    for (int t = 0; t < HOR_; t++) {
        run_cell(p_Gt, p_y, C_, p_hA, p_hA,
                 p_Wp + OFF_D0G, w[9], p_Wp + OFF_D0U, w[11],
                 p_X0, p_Y0, DINR0, DINP0);
        run_cell(p_Gt, p_hA, H_, p_hB, p_hB,
                 p_Wp + OFF_D1G, w[13], p_Wp + OFF_D1U, w[15],
                 p_X1, p_Y1, DINR1, DINP1);
        k_proj<<<cdiv(M_, 256), 256>>>(projW, projb, t, out);
    }
}

// round 5
// speedup vs baseline: 9.8786x; 2.2638x over previous
#include <cuda_runtime.h>
#include <cuda_fp16.h>
#include <math.h>
#include <stdint.h>

// ---------------------------------------------------------------------------
// GCGRU encoder-decoder. FP16 tensor cores (mma.m16n8k16, fp32 accum),
// ldmatrix fragment loads, cp.async double-buffered tiles.
//
// Layouts (all half):
//   g_X*  : (N, din_p, B)        stage-1 input, pad cols zero
//   g_Y*  : (slot, N, din_p, B)  stage-1 output for supports {1,2,4,5};
//                                identity supports (0,3) read from g_X.
//   g_Gt  : (slot, N, N)         4 non-identity supports
//   g_Wp  : padded (K*din_p, outd) weights
// ---------------------------------------------------------------------------

#define N_    1024
#define B_    64
#define T_    12
#define HOR_  12
#define C_    2
#define H_    64
#define K_    6

#define NBH_  (N_ * B_ * H_)
#define M_    (N_ * B_)

#define DINR0 66
#define DINP0 80
#define DINR1 128
#define DINP1 128

// ------------------------- scratch (device globals) -------------------------
__device__ float  g_xT[T_ * N_ * B_ * C_];
__device__ float  g_seq[T_ * N_ * B_ * H_];
__device__ float  g_hA[NBH_];
__device__ float  g_hB[NBH_];
__device__ __half g_X0[N_ * DINP0 * B_];
__device__ __half g_X1[N_ * DINP1 * B_];
__device__ __half g_Y0[4ll * N_ * DINP0 * B_];
__device__ __half g_Y1[4ll * N_ * DINP1 * B_];
__device__ float  g_zr[(size_t)M_ * 2 * H_];
__device__ float  g_y[M_ * C_];
__device__ __half g_Gt[4 * N_ * N_];
__device__ __half g_Wp[479232];

// ------------------------------ helpers -------------------------------------
__device__ __forceinline__ void mma_f16(float* c, const uint32_t* a,
                                        const uint32_t* b) {
    asm volatile(
        "mma.sync.aligned.m16n8k16.row.col.f32.f16.f16.f32 "
        "{%0,%1,%2,%3}, {%4,%5,%6,%7}, {%8,%9}, {%0,%1,%2,%3};\n"
        : "+f"(c[0]), "+f"(c[1]), "+f"(c[2]), "+f"(c[3])
        : "r"(a[0]), "r"(a[1]), "r"(a[2]), "r"(a[3]), "r"(b[0]), "r"(b[1]));
}

__device__ __forceinline__ void ldmx4(uint32_t* r, const void* p) {
    uint32_t a = (uint32_t)__cvta_generic_to_shared(p);
    asm volatile("ldmatrix.sync.aligned.m8n8.x4.shared.b16 {%0,%1,%2,%3}, [%4];"
                 : "=r"(r[0]), "=r"(r[1]), "=r"(r[2]), "=r"(r[3]) : "r"(a));
}
__device__ __forceinline__ void ldmx4t(uint32_t* r, const void* p) {
    uint32_t a = (uint32_t)__cvta_generic_to_shared(p);
    asm volatile("ldmatrix.sync.aligned.m8n8.x4.trans.shared.b16 {%0,%1,%2,%3}, [%4];"
                 : "=r"(r[0]), "=r"(r[1]), "=r"(r[2]), "=r"(r[3]) : "r"(a));
}

__device__ __forceinline__ void cp16(void* dst, const void* src) {
    uint32_t d = (uint32_t)__cvta_generic_to_shared(dst);
    asm volatile("cp.async.ca.shared.global [%0], [%1], 16;\n"
                 :: "r"(d), "l"(src));
}
__device__ __forceinline__ void cp_commit() {
    asm volatile("cp.async.commit_group;\n");
}
template <int n>
__device__ __forceinline__ void cp_wait() {
    asm volatile("cp.async.wait_group %0;\n" :: "n"(n));
}

// ------------------------------ prep kernels --------------------------------

__global__ void k_prep_G(const float* __restrict__ G) {
    int idx = blockIdx.x * blockDim.x + threadIdx.x;
    if (idx >= 4 * N_ * N_) return;
    int s = idx / (N_ * N_);
    int r = idx - s * (N_ * N_);
    int kidx = s + 1 + (s >> 1);   // {1,2,4,5}
    g_Gt[idx] = __float2half_rn(G[(size_t)kidx * N_ * N_ + r]);
}

__global__ void k_prep_W(const float* __restrict__ src, __half* __restrict__ dst,
                         int din_r, int din_p, int outd) {
    int idx = blockIdx.x * blockDim.x + threadIdx.x;
    int total = K_ * din_p * outd;
    if (idx >= total) return;
    int o = idx % outd;
    int row = idx / outd;
    int k = row / din_p;
    int f = row - k * din_p;
    dst[idx] = (f < din_r) ? __float2half_rn(src[(size_t)(k * din_r + f) * outd + o])
                           : __float2half_rn(0.f);
}

// ------------------------------ data movement -------------------------------

// x (B,T,N,C) -> g_xT (T,N,B,C)
__global__ void k_transpose_x(const float* __restrict__ x) {
    int idx = blockIdx.x * blockDim.x + threadIdx.x;
    const int total = B_ * T_ * N_ * C_;
    if (idx >= total) return;
    int c = idx % C_;
    int i = (idx / C_) % N_;
    int t = (idx / (C_ * N_)) % T_;
    int b = idx / (C_ * N_ * T_);
    g_xT[(((size_t)t * N_ + i) * B_ + b) * C_ + c] = x[idx];
}

// Gate-pass concat: X[i][f][b] = concat(x,h), f < din_r, fp16-rounded.
__global__ void k_concat_full(const float* __restrict__ xin, int dinx,
                              const float* __restrict__ h,
                              __half* __restrict__ X, int din_r, int din_p) {
    int idx = blockIdx.x * blockDim.x + threadIdx.x;
    int total = N_ * din_r * B_;
    if (idx >= total) return;
    int b = idx & 63;
    int f = (idx >> 6) % din_r;
    int i = idx / (64 * din_r);
    int m = i * B_ + b;
    float v;
    if (f < dinx) v = xin[(size_t)m * dinx + f];
    else          v = h ? h[(size_t)m * H_ + (f - dinx)] : 0.f;
    X[((size_t)i * din_p + f) * B_ + b] = __float2half_rn(v);
}

// Candidate-pass concat: overwrite h-part with r*h.
__global__ void k_concat_h(const float* __restrict__ h, int dinx,
                           __half* __restrict__ X, int din_p) {
    int idx = blockIdx.x * blockDim.x + threadIdx.x;
    int total = N_ * H_ * B_;
    if (idx >= total) return;
    int b = idx & 63;
    int j = (idx >> 6) & 63;
    int i = idx >> 12;
    int m = i * B_ + b;
    float v = 0.f;
    if (h) v = h[(size_t)m * H_ + j] * g_zr[(size_t)m * (2 * H_) + H_ + j];
    X[((size_t)i * din_p + (dinx + j)) * B_ + b] = __float2half_rn(v);
}

// ------------------------------ stage-1 GEMM --------------------------------
// Y[s] = G[s] @ X over columns [col_off, col_off + gridX*128).
// BM=128, BN=128, BK=32, 8 warps (4x2), warp tile 32x64, fp16 mma m16n8k16.
__global__ __launch_bounds__(256)
void k_gemm1(const __half* __restrict__ Gt, const __half* __restrict__ X,
             __half* __restrict__ Y, int col_off, int ldp) {
    __shared__ __align__(16) __half As[2][128][40];   // BK=32 + pad 8
    __shared__ __align__(16) __half Bs[2][32][136];   // BN=128 + pad 8

    const int s = blockIdx.z;
    const __half* A = Gt + (size_t)s * N_ * N_;
    const int m0 = blockIdx.y * 128;
    const int n0 = col_off + blockIdx.x * 128;
    const int tid = threadIdx.x;
    const int lane = tid & 31;
    const int warp = tid >> 5;
    const int wm = (warp & 3) * 32;
    const int wn = (warp >> 2) * 64;
    const int gq = lane >> 2;
    const int t4 = lane & 3;

    float acc[2][8][4];
#pragma unroll
    for (int i = 0; i < 2; i++)
#pragma unroll
        for (int j = 0; j < 8; j++)
#pragma unroll
            for (int l = 0; l < 4; l++) acc[i][j][l] = 0.f;

    auto load_stage = [&](int buf, int kk0) {
        // A tile 128x32 halves = 8KB = 512 cp16
#pragma unroll
        for (int i = 0; i < 2; i++) {
            int idx = tid + i * 256;
            int row = idx >> 2;
            int seg = (idx & 3) << 3;
            cp16(&As[buf][row][seg], A + (size_t)(m0 + row) * N_ + kk0 + seg);
        }
        // B tile 32x128 halves = 8KB = 512 cp16
#pragma unroll
        for (int i = 0; i < 2; i++) {
            int idx = tid + i * 256;
            int r = idx >> 4;
            int seg = (idx & 15) << 3;
            cp16(&Bs[buf][r][seg], X + (size_t)(kk0 + r) * ldp + n0 + seg);
        }
    };

    load_stage(0, 0);
    cp_commit();

    const int KSTEPS = N_ / 32;
    for (int kt = 0; kt < KSTEPS; kt++) {
        int buf = kt & 1;
        if (kt + 1 < KSTEPS) {
            load_stage(buf ^ 1, (kt + 1) * 32);
            cp_commit();
            cp_wait<1>();
        } else {
            cp_wait<0>();
        }
        __syncthreads();

#pragma unroll
        for (int ks = 0; ks < 2; ks++) {
            const int kb = ks * 16;
            uint32_t a[2][4], b[8][2];
            // A frags: As[m][k], non-trans ldmatrix
#pragma unroll
            for (int mt = 0; mt < 2; mt++) {
                ldmx4(a[mt], &As[buf][wm + mt * 16 + (lane & 15)]
                                     [kb + (lane >> 4) * 8]);
            }
            // B frags: Bs[k][n], trans ldmatrix (2 n8-tiles per x4)
#pragma unroll
            for (int p = 0; p < 4; p++) {
                uint32_t r[4];
                ldmx4t(r, &Bs[buf][kb + (lane & 7) + ((lane >> 3) & 1) * 8]
                                  [wn + p * 16 + (lane >> 4) * 8]);
                b[2 * p][0] = r[0]; b[2 * p][1] = r[1];
                b[2 * p + 1][0] = r[2]; b[2 * p + 1][1] = r[3];
            }
#pragma unroll
            for (int mt = 0; mt < 2; mt++)
#pragma unroll
                for (int nt = 0; nt < 8; nt++)
                    mma_f16(acc[mt][nt], a[mt], b[nt]);
        }
        __syncthreads();
    }

    // coalesced half2 stores
#pragma unroll
    for (int mt = 0; mt < 2; mt++) {
        int row = m0 + wm + mt * 16 + gq;
#pragma unroll
        for (int nt = 0; nt < 8; nt++) {
            int xcol = n0 + wn + nt * 8 + t4 * 2;
#pragma unroll
            for (int hh = 0; hh < 2; hh++) {
                int rr = row + hh * 8;
                __half2 v = __floats2half2_rn(acc[mt][nt][hh * 2 + 0],
                                              acc[mt][nt][hh * 2 + 1]);
                *(__half2*)&Y[((size_t)s * N_ + rr) * ldp + xcol] = v;
            }
        }
    }
}

// ------------------------------ stage-2 GEMM --------------------------------
// out = act(A @ W + bias); A rows m=(node,b), cols (k,f) padded.
// A 16-col sub-chunks come from g_X (k=0,3) or g_Y slot (k=1,2,4,5).
// BM=128 (2 nodes), BN=64, BK=32, 8 warps (4x2), warp tile 32x32.
// mode 0: g_zr = sigmoid(.); mode 1: hout = z*tanh(.)+(1-z)*h.
__global__ __launch_bounds__(256)
void k_gemm2(const __half* __restrict__ Xp, const __half* __restrict__ Yp,
             const __half* __restrict__ W, const float* __restrict__ bias,
             int din_p, int outd, int mode,
             const float* __restrict__ hprev, float* __restrict__ hout) {
    __shared__ __align__(16) __half Ask[2][32][136];  // [k][m], m=128 + pad 8
    __shared__ __align__(16) __half Bs[2][32][72];    // [k][n], n=64 + pad 8

    const int m0 = blockIdx.y * 128;
    const int i0 = m0 >> 6;            // base node (2 nodes per block)
    const int n0 = blockIdx.x * 64;
    const int tid = threadIdx.x;
    const int lane = tid & 31;
    const int warp = tid >> 5;
    const int wm = (warp & 3) * 32;
    const int wn = (warp >> 2) * 32;
    const int gq = lane >> 2;
    const int t4 = lane & 3;
    const int ldp = din_p * B_;

    float acc[2][4][4];
#pragma unroll
    for (int i = 0; i < 2; i++)
#pragma unroll
        for (int j = 0; j < 4; j++)
#pragma unroll
            for (int l = 0; l < 4; l++) acc[i][j][l] = 0.f;

    auto load_stage = [&](int buf, int kt) {
        // two 16-col sub-chunks; each lies inside one support slot (16|din_p)
#pragma unroll
        for (int s16 = 0; s16 < 2; s16++) {
            int kk16 = kt * 32 + s16 * 16;
            int k = kk16 / din_p;
            int f0 = kk16 - k * din_p;
            const __half* basep;
            if (k == 0 || k == 3) basep = Xp;
            else basep = Yp + (size_t)((k < 3) ? k - 1 : k - 2) * N_ * ldp;
            // 16 f-rows x 128 m halves = 4KB = 256 cp16
            int j = tid >> 4;                 // f row 0..15
            int q = tid & 15;
            int node = q >> 3;
            int ch = (q & 7) << 3;
            cp16(&Ask[buf][s16 * 16 + j][node * 64 + ch],
                 basep + ((size_t)(i0 + node) * din_p + f0 + j) * B_ + ch);
        }
        // W tile 32x64 halves = 4KB = 256 cp16
        {
            int kk0 = kt * 32;
            int r = tid >> 3;                 // 0..31
            int ch = (tid & 7) << 3;          // 0..56
            cp16(&Bs[buf][r][ch], W + (size_t)(kk0 + r) * outd + n0 + ch);
        }
    };

    load_stage(0, 0);
    cp_commit();

    const int KSTEPS = (K_ * din_p) >> 5;
    for (int kt = 0; kt < KSTEPS; kt++) {
        int buf = kt & 1;
        if (kt + 1 < KSTEPS) {
            load_stage(buf ^ 1, kt + 1);
            cp_commit();
            cp_wait<1>();
        } else {
            cp_wait<0>();
        }
        __syncthreads();

#pragma unroll
        for (int ks = 0; ks < 2; ks++) {
            const int kb = ks * 16;
            uint32_t a[2][4], b[4][2];
            // A frags from Ask[k][m] via trans ldmatrix
#pragma unroll
            for (int mt = 0; mt < 2; mt++) {
                ldmx4t(a[mt], &Ask[buf][kb + (lane & 7) + ((lane >> 4) & 1) * 8]
                                       [wm + mt * 16 + ((lane >> 3) & 1) * 8]);
            }
            // B frags from Bs[k][n] via trans ldmatrix
#pragma unroll
            for (int p = 0; p < 2; p++) {
                uint32_t r[4];
                ldmx4t(r, &Bs[buf][kb + (lane & 7) + ((lane >> 3) & 1) * 8]
                                  [wn + p * 16 + (lane >> 4) * 8]);
                b[2 * p][0] = r[0]; b[2 * p][1] = r[1];
                b[2 * p + 1][0] = r[2]; b[2 * p + 1][1] = r[3];
            }
#pragma unroll
            for (int mt = 0; mt < 2; mt++)
#pragma unroll
                for (int nt = 0; nt < 4; nt++)
                    mma_f16(acc[mt][nt], a[mt], b[nt]);
        }
        __syncthreads();
    }

#pragma unroll
    for (int mt = 0; mt < 2; mt++) {
        int row = m0 + wm + mt * 16 + gq;
#pragma unroll
        for (int nt = 0; nt < 4; nt++) {
            int nb = n0 + wn + nt * 8 + t4 * 2;
#pragma unroll
            for (int hh = 0; hh < 2; hh++) {
                size_t m = (size_t)(row + hh * 8);
#pragma unroll
                for (int cc = 0; cc < 2; cc++) {
                    int n = nb + cc;
                    float v = acc[mt][nt][hh * 2 + cc] + bias[n];
                    if (mode == 0) {
                        g_zr[m * (2 * H_) + n] = 1.f / (1.f + expf(-v));
                    } else {
                        float z = g_zr[m * (2 * H_) + n];
                        float hold = hprev ? hprev[m * H_ + n] : 0.f;
                        hout[m * H_ + n] = z * tanhf(v) + (1.f - z) * hold;
                    }
                }
            }
        }
    }
}

// Projection + output scatter + decoder feedback.
__global__ void k_proj(const float* __restrict__ projW,
                       const float* __restrict__ projb,
                       int t, float* __restrict__ out) {
    int m = blockIdx.x * blockDim.x + threadIdx.x;
    if (m >= M_) return;
    int i = m / B_;
    int b = m - i * B_;
    float a0 = projb[0], a1 = projb[1];
    const float* hv = &g_hB[(size_t)m * H_];
#pragma unroll
    for (int j = 0; j < H_; j++) {
        float h = hv[j];
        a0 += h * projW[j * 2 + 0];
        a1 += h * projW[j * 2 + 1];
    }
    g_y[(size_t)m * C_ + 0] = a0;
    g_y[(size_t)m * C_ + 1] = a1;
    size_t o = ((((size_t)b * HOR_ + t) * N_) + i) * C_;
    out[o + 0] = a0;
    out[o + 1] = a1;
}

// ------------------------------ host side -----------------------------------

static inline int cdiv(int a, int b) { return (a + b - 1) / b; }

// padded weight offsets inside g_Wp (element counts)
#define OFF_E0G 0
#define OFF_E0U 61440
#define OFF_D0G 92160
#define OFF_D0U 153600
#define OFF_E1G 184320
#define OFF_E1U 282624
#define OFF_D1G 331776
#define OFF_D1U 430080

static void run_cell(const __half* Gt,
                     const float* xin, int dinx,
                     const float* hprev, float* hout,
                     const __half* Wg, const float* bg,
                     const __half* Wu, const float* bu,
                     __half* Xp, __half* Yp, int din_r, int din_p) {
    const int ldp = din_p * B_;

    // gate pass
    k_concat_full<<<cdiv(N_ * din_r * B_, 256), 256>>>(xin, dinx, hprev,
                                                       Xp, din_r, din_p);
    dim3 g1((din_r * B_) / 128, N_ / 128, 4);
    k_gemm1<<<g1, 256>>>(Gt, Xp, Yp, 0, ldp);
    k_gemm2<<<dim3(2, M_ / 128), 256>>>(Xp, Yp, Wg, bg, din_p, 2 * H_, 0,
                                        nullptr, nullptr);

    // candidate pass: only h columns recomputed
    k_concat_h<<<cdiv(N_ * H_ * B_, 256), 256>>>(hprev, dinx, Xp, din_p);
    dim3 g1h((H_ * B_) / 128, N_ / 128, 4);
    k_gemm1<<<g1h, 256>>>(Gt, Xp, Yp, dinx * B_, ldp);
    k_gemm2<<<dim3(1, M_ / 128), 256>>>(Xp, Yp, Wu, bu, din_p, H_, 1,
                                        hprev, hout);
}

extern "C" void kernel_launch(void* const* d_in, const int* in_sizes, int n_in,
                              void* d_out, int out_size) {
    (void)in_sizes; (void)n_in; (void)out_size;

    const float* x = (const float*)d_in[0];
    const float* G = (const float*)d_in[1];
    const float* w[16];
    for (int i = 0; i < 16; i++) w[i] = (const float*)d_in[2 + i];
    const float* projW = (const float*)d_in[18];
    const float* projb = (const float*)d_in[19];
    float* out = (float*)d_out;

    float *p_xT, *p_seq, *p_hA, *p_hB, *p_y;
    __half *p_X0, *p_X1, *p_Y0, *p_Y1, *p_Gt, *p_Wp;
    cudaGetSymbolAddress((void**)&p_xT,  g_xT);
    cudaGetSymbolAddress((void**)&p_seq, g_seq);
    cudaGetSymbolAddress((void**)&p_hA,  g_hA);
    cudaGetSymbolAddress((void**)&p_hB,  g_hB);
    cudaGetSymbolAddress((void**)&p_y,   g_y);
    cudaGetSymbolAddress((void**)&p_X0,  g_X0);
    cudaGetSymbolAddress((void**)&p_X1,  g_X1);
    cudaGetSymbolAddress((void**)&p_Y0,  g_Y0);
    cudaGetSymbolAddress((void**)&p_Y1,  g_Y1);
    cudaGetSymbolAddress((void**)&p_Gt,  g_Gt);
    cudaGetSymbolAddress((void**)&p_Wp,  g_Wp);

    // prep: round G, pad+round weights (all to fp16)
    k_prep_G<<<cdiv(4 * N_ * N_, 256), 256>>>(G);
    k_prep_W<<<cdiv(K_ * DINP0 * 128, 256), 256>>>(w[0],  p_Wp + OFF_E0G, DINR0, DINP0, 128);
    k_prep_W<<<cdiv(K_ * DINP0 *  64, 256), 256>>>(w[2],  p_Wp + OFF_E0U, DINR0, DINP0,  64);
    k_prep_W<<<cdiv(K_ * DINP1 * 128, 256), 256>>>(w[4],  p_Wp + OFF_E1G, DINR1, DINP1, 128);
    k_prep_W<<<cdiv(K_ * DINP1 *  64, 256), 256>>>(w[6],  p_Wp + OFF_E1U, DINR1, DINP1,  64);
    k_prep_W<<<cdiv(K_ * DINP0 * 128, 256), 256>>>(w[8],  p_Wp + OFF_D0G, DINR0, DINP0, 128);
    k_prep_W<<<cdiv(K_ * DINP0 *  64, 256), 256>>>(w[10], p_Wp + OFF_D0U, DINR0, DINP0,  64);
    k_prep_W<<<cdiv(K_ * DINP1 * 128, 256), 256>>>(w[12], p_Wp + OFF_D1G, DINR1, DINP1, 128);
    k_prep_W<<<cdiv(K_ * DINP1 *  64, 256), 256>>>(w[14], p_Wp + OFF_D1U, DINR1, DINP1,  64);

    {
        int total = B_ * T_ * N_ * C_;
        k_transpose_x<<<cdiv(total, 256), 256>>>(x);
    }

    // encoder layer 0 (din 66 -> padded 80)
    for (int t = 0; t < T_; t++) {
        const float* xin   = p_xT + (size_t)t * N_ * B_ * C_;
        const float* hprev = (t == 0) ? nullptr : p_seq + (size_t)(t - 1) * NBH_;
        float* hout        = p_seq + (size_t)t * NBH_;
        run_cell(p_Gt, xin, C_, hprev, hout,
                 p_Wp + OFF_E0G, w[1], p_Wp + OFF_E0U, w[3],
                 p_X0, p_Y0, DINR0, DINP0);
    }

    // encoder layer 1 (din 128)
    for (int t = 0; t < T_; t++) {
        const float* xin   = p_seq + (size_t)t * NBH_;
        const float* hprev = (t == 0) ? nullptr : p_hB;
        run_cell(p_Gt, xin, H_, hprev, p_hB,
                 p_Wp + OFF_E1G, w[5], p_Wp + OFF_E1U, w[7],
                 p_X1, p_Y1, DINR1, DINP1);
    }

    // decoder init
    cudaMemcpyAsync(p_hA, p_seq + (size_t)(T_ - 1) * NBH_,
                    (size_t)NBH_ * sizeof(float), cudaMemcpyDeviceToDevice);
    cudaMemsetAsync(p_y, 0, (size_t)M_ * C_ * sizeof(float));

    // decoder loop
    for (int t = 0; t < HOR_; t++) {
        run_cell(p_Gt, p_y, C_, p_hA, p_hA,
                 p_Wp + OFF_D0G, w[9], p_Wp + OFF_D0U, w[11],
                 p_X0, p_Y0, DINR0, DINP0);
        run_cell(p_Gt, p_hA, H_, p_hB, p_hB,
                 p_Wp + OFF_D1G, w[13], p_Wp + OFF_D1U, w[15],
                 p_X1, p_Y1, DINR1, DINP1);
        k_proj<<<cdiv(M_, 256), 256>>>(projW, projb, t, out);
    }
}